// round 6
// baseline (speedup 1.0000x reference)
#include <cuda_runtime.h>

// Problem constants: volume (2,3,96,96,96) fp32 -> (2,3,192,192,192) fp32
#define NB 6
#define N 96
#define NO 192
#define SLICE (N * N)
#define VOL (N * N * N)

// Scratch for xy-prefiltered spline coefficients (21.2 MB)
__device__ float g_coef[NB * VOL];

// ---------------------------------------------------------------------------
// Composite cubic B-spline prefilter: causal o anticausal == symmetric FIR
//   h[k] = sqrt(3) * p^|k|,  p = sqrt(3)-2, truncated at |k|<=12 (~2e-7).
// Left mirror boundary exact via mirrored reads; right boundary exact via
// two-stage (causal FIR -> clamp -> anticausal FIR). Taps are immediates.
// ---------------------------------------------------------------------------
__device__ __forceinline__ float dotH(const float* w) {
    float a =                2.3724122e-7f * w[0];
    a = fmaf(-8.8547113e-7f, w[1],  a);
    a = fmaf( 3.3046232e-6f, w[2],  a);
    a = fmaf(-1.2333006e-5f, w[3],  a);
    a = fmaf( 4.6027405e-5f, w[4],  a);
    a = fmaf(-1.7177666e-4f, w[5],  a);
    a = fmaf( 6.4104185e-4f, w[6],  a);
    a = fmaf(-2.3923958e-3f, w[7],  a);
    a = fmaf( 8.9283344e-3f, w[8],  a);
    a = fmaf(-3.3320996e-2f, w[9],  a);
    a = fmaf( 1.2435565e-1f, w[10], a);
    a = fmaf(-4.6410162e-1f, w[11], a);
    a = fmaf( 1.7320508e0f,  w[12], a);
    a = fmaf(-4.6410162e-1f, w[13], a);
    a = fmaf( 1.2435565e-1f, w[14], a);
    a = fmaf(-3.3320996e-2f, w[15], a);
    a = fmaf( 8.9283344e-3f, w[16], a);
    a = fmaf(-2.3923958e-3f, w[17], a);
    a = fmaf( 6.4104185e-4f, w[18], a);
    a = fmaf(-1.7177666e-4f, w[19], a);
    a = fmaf( 4.6027405e-5f, w[20], a);
    a = fmaf(-1.2333006e-5f, w[21], a);
    a = fmaf( 3.3046232e-6f, w[22], a);
    a = fmaf(-8.8547113e-7f, w[23], a);
    a = fmaf( 2.3724122e-7f, w[24], a);
    return a;
}

__device__ __forceinline__ float dotA(const float* w) {
    float acc =              8.2182750e-7f * w[0];
    acc = fmaf(-3.0674046e-6f, w[1],  acc);
    acc = fmaf( 1.1446578e-5f, w[2],  acc);
    acc = fmaf(-4.2719250e-5f, w[3],  acc);
    acc = fmaf( 1.5943030e-4f, w[4],  acc);
    acc = fmaf(-5.9500220e-4f, w[5],  acc);
    acc = fmaf( 2.2205777e-3f, w[6],  acc);
    acc = fmaf(-8.2873086e-3f, w[7],  acc);
    acc = fmaf( 3.0928657e-2f, w[8],  acc);
    acc = fmaf(-1.1542732e-1f, w[9],  acc);
    acc = fmaf( 4.3078062e-1f, w[10], acc);
    acc = fmaf(-1.6076952e0f,  w[11], acc);
    acc = fmaf( 6.0f,          w[12], acc);
    return acc;
}

__device__ __forceinline__ float dotB(const float* w) {
    float acc =              3.6700780e-8f * w[12];
    acc = fmaf(-1.3697125e-7f, w[11], acc);
    acc = fmaf( 5.1123410e-7f, w[10], acc);
    acc = fmaf(-1.9077630e-6f, w[9],  acc);
    acc = fmaf( 7.1198750e-6f, w[8],  acc);
    acc = fmaf(-2.6571710e-5f, w[7],  acc);
    acc = fmaf( 9.9170000e-5f, w[6],  acc);
    acc = fmaf(-3.7009628e-4f, w[5],  acc);
    acc = fmaf( 1.3812181e-3f, w[4],  acc);
    acc = fmaf(-5.1547761e-3f, w[3],  acc);
    acc = fmaf( 1.9237886e-2f, w[2],  acc);
    acc = fmaf(-7.1796770e-2f, w[1],  acc);
    acc = fmaf( 2.6794919e-1f, w[0],  acc);
    return acc;
}

// One prefilter phase for group g (16 outputs) of a 96-line, stride S.
// Reads bsrc, writes bdst (ping-pong -> no internal barrier needed).
template <int S>
__device__ __forceinline__ void phaseP(const float* bsrc, float* bdst, int g) {
    float yv[16];
    if (g == 0) {  // left edge: composite on mirror-extended reads (exact)
        float w[40];
#pragma unroll
        for (int k = 0; k < 40; ++k) {
            int j = k - 12;
            int idx = j ^ (j >> 31);  // mirror x[-m] = x[m-1]
            w[k] = bsrc[idx * S];
        }
#pragma unroll
        for (int m = 0; m < 16; ++m) yv[m] = dotH(w + m);
    } else if (g < 5) {  // interior
        float w[40];
#pragma unroll
        for (int k = 0; k < 40; ++k) w[k] = bsrc[(g * 16 - 12 + k) * S];
#pragma unroll
        for (int m = 0; m < 16; ++m) yv[m] = dotH(w + m);
    } else {  // right edge: 80..83 composite; 84..95 exact two-stage
        float xw[28];
#pragma unroll
        for (int k = 0; k < 28; ++k) xw[k] = bsrc[(68 + k) * S];
#pragma unroll
        for (int m = 0; m < 4; ++m) yv[m] = dotH(xw + m);
        float ce[24];
#pragma unroll
        for (int j = 0; j < 12; ++j) ce[j] = dotA(xw + 4 + j);
#pragma unroll
        for (int j = 12; j < 24; ++j) ce[j] = ce[11];
#pragma unroll
        for (int m = 0; m < 12; ++m) yv[4 + m] = dotB(ce + m);
    }
#pragma unroll
    for (int m = 0; m < 16; ++m) bdst[(g * 16 + m) * S] = yv[m];
}

#define PF_THREADS 576
#define PF_SMEM (2 * N * (N + 1) * 4)

// ---------------------------------------------------------------------------
// Kernel A: prefilter x then y, one CTA per (b,c,z) slice. (unchanged)
// ---------------------------------------------------------------------------
__global__ void __launch_bounds__(PF_THREADS, 2) prefilter_xy(const float* __restrict__ in) {
    extern __shared__ float sm[];
    float* s0 = sm;
    float* s1 = sm + N * (N + 1);
    const int slice = blockIdx.x;
    const float* src = in + (long)slice * SLICE;
    float* dst = g_coef + (long)slice * SLICE;
    const int t = threadIdx.x;
    const int g = t / N, l = t % N;

#pragma unroll
    for (int i = 0; i < 16; ++i) {
        int r = g * 16 + i;
        s0[r * (N + 1) + l] = src[r * N + l];
    }
    __syncthreads();

    phaseP<1>(&s0[l * (N + 1)], &s1[l * (N + 1)], g);  // x: row l
    __syncthreads();
    phaseP<N + 1>(&s1[l], &s0[l], g);                  // y: column l

#pragma unroll
    for (int i = 0; i < 16; ++i) {
        int r = g * 16 + i;
        dst[r * N + l] = s0[r * (N + 1) + l];
    }
}

// ---------------------------------------------------------------------------
// Kernel B (fused): z-prefilter + separable 3D x2 upsample.
// Tile: full z (96) x 8 y x 16 x coefficients (+2 halo y/x, edge clamp).
//   1. load raw xy-filtered tile [96][12][20] into smem
//   2. z-composite FIR in smem (240 columns x 6 groups, exact boundaries)
//   3. 12 z-chunks: stage X -> stage Y -> stage Z (STG.128 streaming)
// smem: s_cf [96][12][20] filtered; raw buffer aliased by s_x/s_y after use.
// ---------------------------------------------------------------------------
#define IY 12
#define IX 20
#define SXW 36
#define FT 512
#define COLS (IY * IX)  // 240

#define S_CF_SZ (96 * COLS)                 // 23040 floats
#define FUS_SMEM ((2 * S_CF_SZ) * 4)        // 184320 bytes

#define KA 0.00260416674427688122f
#define KB 0.0703125f
#define KC 0.31510416666666667f
#define KD 0.61197916666666663f

#define UP_EVEN(a, b_, c_, d_) fmaf(KA, (a), fmaf(KC, (b_), fmaf(KD, (c_), KB * (d_))))
#define UP_ODD(a, b_, c_, d_)  fmaf(KB, (a), fmaf(KD, (b_), fmaf(KC, (c_), KA * (d_))))

__device__ __forceinline__ float4 up_even4(float4 a, float4 b, float4 c, float4 d) {
    float4 r;
    r.x = UP_EVEN(a.x, b.x, c.x, d.x);
    r.y = UP_EVEN(a.y, b.y, c.y, d.y);
    r.z = UP_EVEN(a.z, b.z, c.z, d.z);
    r.w = UP_EVEN(a.w, b.w, c.w, d.w);
    return r;
}
__device__ __forceinline__ float4 up_odd4(float4 a, float4 b, float4 c, float4 d) {
    float4 r;
    r.x = UP_ODD(a.x, b.x, c.x, d.x);
    r.y = UP_ODD(a.y, b.y, c.y, d.y);
    r.z = UP_ODD(a.z, b.z, c.z, d.z);
    r.w = UP_ODD(a.w, b.w, c.w, d.w);
    return r;
}

__global__ void __launch_bounds__(FT) upsample_fused(float* __restrict__ out) {
    extern __shared__ float sm[];
    float* s_cf = sm;                 // [96][12][20] z-filtered coefs
    float* s_c = sm + S_CF_SZ;        // [96][12][20] raw (dead after z-filter)
    float* s_x = sm + S_CF_SZ;        // [12][12][36] = 5184 (alias raw)
    float* s_y = sm + S_CF_SZ + 5184; // [12][16][32] = 6144 (alias raw)

    const int xb = blockIdx.x;   // 0..5
    const int yb = blockIdx.y;   // 0..11
    const int bc = blockIdx.z;   // 0..5
    const int t = threadIdx.x;

    const float* src = g_coef + (long)bc * VOL;
    const int gy0 = yb * 8 - 2, gx0 = xb * 16 - 2;

    // 1. Load raw tile [96][12][20] with y/x edge clamp
    for (int e = t; e < S_CF_SZ; e += FT) {
        int lx = e % IX;
        int r = e / IX;
        int ly = r % IY;
        int lz = r / IY;
        int gy = min(max(gy0 + ly, 0), N - 1);
        int gx = min(max(gx0 + lx, 0), N - 1);
        s_c[e] = src[((long)lz * N + gy) * N + gx];
    }
    __syncthreads();

    // 2. z-composite FIR: 240 columns x 6 groups = 1440 tasks
    for (int e = t; e < 6 * COLS; e += FT) {
        int col = e % COLS;
        int g = e / COLS;
        phaseP<COLS>(s_c + col, s_cf + col, g);
    }
    __syncthreads();  // s_c dead; s_x/s_y may now overwrite it

    // 3. Upsample in 12 z-chunks of 8 coef -> 16 output planes each
    for (int ci = 0; ci < 12; ++ci) {
        // Stage X: 12(z) x 12(y) lines x 4 quads = 576 tasks
        for (int e = t; e < 576; e += FT) {
            int q = e & 3;
            int line = e >> 2;             // lz*12 + ly
            int lz = line / IY, ly = line % IY;
            int zc = min(max(ci * 8 - 2 + lz, 0), N - 1);
            const float* row = s_cf + (zc * IY + ly) * IX + 4 * q;
            const float4 p0 = *(const float4*)row;
            const float4 p1 = *(const float4*)(row + 4);
            const float v0 = p0.x, v1 = p0.y, v2 = p0.z, v3 = p0.w;
            const float v4 = p1.x, v5 = p1.y, v6 = p1.z, v7 = p1.w;
            float4 r0, r1;
            r0.x = UP_EVEN(v0, v1, v2, v3);
            r0.y = UP_ODD(v1, v2, v3, v4);
            r0.z = UP_EVEN(v1, v2, v3, v4);
            r0.w = UP_ODD(v2, v3, v4, v5);
            r1.x = UP_EVEN(v2, v3, v4, v5);
            r1.y = UP_ODD(v3, v4, v5, v6);
            r1.z = UP_EVEN(v3, v4, v5, v6);
            r1.w = UP_ODD(v4, v5, v6, v7);
            *(float4*)&s_x[line * SXW + 8 * q] = r0;
            *(float4*)&s_x[line * SXW + 8 * q + 4] = r1;
        }
        __syncthreads();

        // Stage Y: 12(lz) x 32(xo) = 384 tasks; window 12 -> 16 y-outputs
        for (int e = t; e < 384; e += FT) {
            const int xo = e & 31, lz = e >> 5;
            float u[IY];
#pragma unroll
            for (int h = 0; h < IY; ++h) u[h] = s_x[(lz * IY + h) * SXW + xo];
#pragma unroll
            for (int h = 0; h < 8; ++h) {
                s_y[(lz * 16 + 2 * h) * 32 + xo] = UP_EVEN(u[h], u[h + 1], u[h + 2], u[h + 3]);
                s_y[(lz * 16 + 2 * h + 1) * 32 + xo] = UP_ODD(u[h + 1], u[h + 2], u[h + 3], u[h + 4]);
            }
        }
        __syncthreads();

        // Stage Z: 8(h) x 16(yo) x 8(xq) = 1024 tasks -> 2 float4 stores each
        for (int e = t; e < 1024; e += FT) {
            const int xq = e & 7, yo = (e >> 3) & 15, h = e >> 7;  // h 0..7
            float4 u0 = *(const float4*)&s_y[((h + 0) * 16 + yo) * 32 + 4 * xq];
            float4 u1 = *(const float4*)&s_y[((h + 1) * 16 + yo) * 32 + 4 * xq];
            float4 u2 = *(const float4*)&s_y[((h + 2) * 16 + yo) * 32 + 4 * xq];
            float4 u3 = *(const float4*)&s_y[((h + 3) * 16 + yo) * 32 + 4 * xq];
            float4 u4 = *(const float4*)&s_y[((h + 4) * 16 + yo) * 32 + 4 * xq];
            float4 o0 = up_even4(u0, u1, u2, u3);
            float4 o1 = up_odd4(u1, u2, u3, u4);
            const long zo = (long)ci * 16 + 2 * h;
            const long base_out = (((long)bc * NO + zo) * NO + (long)yb * 16 + yo) * NO +
                                  (long)xb * 32 + 4 * xq;
            __stcs((float4*)&out[base_out], o0);
            __stcs((float4*)&out[base_out + NO * NO], o1);
        }
        __syncthreads();  // s_y reads done before next chunk overwrites
    }
}

// ---------------------------------------------------------------------------
extern "C" void kernel_launch(void* const* d_in, const int* in_sizes, int n_in,
                              void* d_out, int out_size) {
    const float* in = (const float*)d_in[0];
    float* out = (float*)d_out;

    cudaFuncSetAttribute(prefilter_xy, cudaFuncAttributeMaxDynamicSharedMemorySize, PF_SMEM);
    cudaFuncSetAttribute(upsample_fused, cudaFuncAttributeMaxDynamicSharedMemorySize, FUS_SMEM);

    prefilter_xy<<<NB * N, PF_THREADS, PF_SMEM>>>(in);
    upsample_fused<<<dim3(N / 16, N / 8, NB), FT, FUS_SMEM>>>(out);
}

// round 7
// speedup vs baseline: 1.3232x; 1.3232x over previous
#include <cuda_runtime.h>

// Problem constants: volume (2,3,96,96,96) fp32 -> (2,3,192,192,192) fp32
#define NB 6
#define N 96
#define NO 192
#define SLICE (N * N)
#define VOL (N * N * N)

// Scratch for xy/z-prefiltered spline coefficients (21.2 MB)
__device__ float g_coef[NB * VOL];

// ---------------------------------------------------------------------------
// Composite cubic B-spline prefilter: causal o anticausal == symmetric FIR
//   h[k] = sqrt(3) * p^|k|,  p = sqrt(3)-2, truncated at |k|<=12 (~2e-7).
// Left mirror boundary exact via mirrored reads; right boundary exact via
// two-stage (causal FIR -> clamp -> anticausal FIR). Taps are immediates.
// ---------------------------------------------------------------------------
__device__ __forceinline__ float dotH(const float* w) {
    float a =                2.3724122e-7f * w[0];
    a = fmaf(-8.8547113e-7f, w[1],  a);
    a = fmaf( 3.3046232e-6f, w[2],  a);
    a = fmaf(-1.2333006e-5f, w[3],  a);
    a = fmaf( 4.6027405e-5f, w[4],  a);
    a = fmaf(-1.7177666e-4f, w[5],  a);
    a = fmaf( 6.4104185e-4f, w[6],  a);
    a = fmaf(-2.3923958e-3f, w[7],  a);
    a = fmaf( 8.9283344e-3f, w[8],  a);
    a = fmaf(-3.3320996e-2f, w[9],  a);
    a = fmaf( 1.2435565e-1f, w[10], a);
    a = fmaf(-4.6410162e-1f, w[11], a);
    a = fmaf( 1.7320508e0f,  w[12], a);
    a = fmaf(-4.6410162e-1f, w[13], a);
    a = fmaf( 1.2435565e-1f, w[14], a);
    a = fmaf(-3.3320996e-2f, w[15], a);
    a = fmaf( 8.9283344e-3f, w[16], a);
    a = fmaf(-2.3923958e-3f, w[17], a);
    a = fmaf( 6.4104185e-4f, w[18], a);
    a = fmaf(-1.7177666e-4f, w[19], a);
    a = fmaf( 4.6027405e-5f, w[20], a);
    a = fmaf(-1.2333006e-5f, w[21], a);
    a = fmaf( 3.3046232e-6f, w[22], a);
    a = fmaf(-8.8547113e-7f, w[23], a);
    a = fmaf( 2.3724122e-7f, w[24], a);
    return a;
}

__device__ __forceinline__ float dotA(const float* w) {
    float acc =              8.2182750e-7f * w[0];
    acc = fmaf(-3.0674046e-6f, w[1],  acc);
    acc = fmaf( 1.1446578e-5f, w[2],  acc);
    acc = fmaf(-4.2719250e-5f, w[3],  acc);
    acc = fmaf( 1.5943030e-4f, w[4],  acc);
    acc = fmaf(-5.9500220e-4f, w[5],  acc);
    acc = fmaf( 2.2205777e-3f, w[6],  acc);
    acc = fmaf(-8.2873086e-3f, w[7],  acc);
    acc = fmaf( 3.0928657e-2f, w[8],  acc);
    acc = fmaf(-1.1542732e-1f, w[9],  acc);
    acc = fmaf( 4.3078062e-1f, w[10], acc);
    acc = fmaf(-1.6076952e0f,  w[11], acc);
    acc = fmaf( 6.0f,          w[12], acc);
    return acc;
}

__device__ __forceinline__ float dotB(const float* w) {
    float acc =              3.6700780e-8f * w[12];
    acc = fmaf(-1.3697125e-7f, w[11], acc);
    acc = fmaf( 5.1123410e-7f, w[10], acc);
    acc = fmaf(-1.9077630e-6f, w[9],  acc);
    acc = fmaf( 7.1198750e-6f, w[8],  acc);
    acc = fmaf(-2.6571710e-5f, w[7],  acc);
    acc = fmaf( 9.9170000e-5f, w[6],  acc);
    acc = fmaf(-3.7009628e-4f, w[5],  acc);
    acc = fmaf( 1.3812181e-3f, w[4],  acc);
    acc = fmaf(-5.1547761e-3f, w[3],  acc);
    acc = fmaf( 1.9237886e-2f, w[2],  acc);
    acc = fmaf(-7.1796770e-2f, w[1],  acc);
    acc = fmaf( 2.6794919e-1f, w[0],  acc);
    return acc;
}

// One prefilter phase for group g (16 outputs) of a 96-line, stride S.
// Reads bsrc, writes bdst (ping-pong -> no internal barrier needed).
template <int S>
__device__ __forceinline__ void phaseP(const float* bsrc, float* bdst, int g) {
    float yv[16];
    if (g == 0) {  // left edge: composite on mirror-extended reads (exact)
        float w[40];
#pragma unroll
        for (int k = 0; k < 40; ++k) {
            int j = k - 12;
            int idx = j ^ (j >> 31);  // mirror x[-m] = x[m-1]
            w[k] = bsrc[idx * S];
        }
#pragma unroll
        for (int m = 0; m < 16; ++m) yv[m] = dotH(w + m);
    } else if (g < 5) {  // interior
        float w[40];
#pragma unroll
        for (int k = 0; k < 40; ++k) w[k] = bsrc[(g * 16 - 12 + k) * S];
#pragma unroll
        for (int m = 0; m < 16; ++m) yv[m] = dotH(w + m);
    } else {  // right edge: 80..83 composite; 84..95 exact two-stage
        float xw[28];
#pragma unroll
        for (int k = 0; k < 28; ++k) xw[k] = bsrc[(68 + k) * S];
#pragma unroll
        for (int m = 0; m < 4; ++m) yv[m] = dotH(xw + m);
        float ce[24];
#pragma unroll
        for (int j = 0; j < 12; ++j) ce[j] = dotA(xw + 4 + j);
#pragma unroll
        for (int j = 12; j < 24; ++j) ce[j] = ce[11];
#pragma unroll
        for (int m = 0; m < 12; ++m) yv[4 + m] = dotB(ce + m);
    }
#pragma unroll
    for (int m = 0; m < 16; ++m) bdst[(g * 16 + m) * S] = yv[m];
}

#define PF_THREADS 576  // 96 lines x 6 groups
#define PF_SMEM (2 * N * (N + 1) * 4)  // ping-pong pair, bytes

// ---------------------------------------------------------------------------
// Kernel A: prefilter x then y, one CTA per (b,c,z) slice.
// 3 CTAs/SM target (54 warps): smem 3 x 74.5KB = 223.5KB <= 228KB.
// ---------------------------------------------------------------------------
__global__ void __launch_bounds__(PF_THREADS, 3) prefilter_xy(const float* __restrict__ in) {
    extern __shared__ float sm[];
    float* s0 = sm;
    float* s1 = sm + N * (N + 1);
    const int slice = blockIdx.x;
    const float* src = in + (long)slice * SLICE;
    float* dst = g_coef + (long)slice * SLICE;
    const int t = threadIdx.x;
    const int g = t / N, l = t % N;

#pragma unroll
    for (int i = 0; i < 16; ++i) {
        int r = g * 16 + i;
        s0[r * (N + 1) + l] = src[r * N + l];
    }
    __syncthreads();

    phaseP<1>(&s0[l * (N + 1)], &s1[l * (N + 1)], g);  // x: row l
    __syncthreads();
    phaseP<N + 1>(&s1[l], &s0[l], g);                  // y: column l

    // store reads only elements this thread just wrote -> no barrier
#pragma unroll
    for (int i = 0; i < 16; ++i) {
        int r = g * 16 + i;
        dst[r * N + l] = s0[r * (N + 1) + l];
    }
}

// ---------------------------------------------------------------------------
// Kernel B: prefilter along z, one CTA per (b,c,y) slice. 1 barrier.
// ---------------------------------------------------------------------------
__global__ void __launch_bounds__(PF_THREADS, 3) prefilter_z() {
    extern __shared__ float sm[];
    float* s0 = sm;
    float* s1 = sm + N * (N + 1);
    const int bc = blockIdx.x / N;
    const int y = blockIdx.x % N;
    float* base = g_coef + (long)bc * VOL + (long)y * N;
    const int t = threadIdx.x;
    const int g = t / N, l = t % N;  // l = x index

#pragma unroll
    for (int i = 0; i < 16; ++i) {
        int z = g * 16 + i;
        s0[z * (N + 1) + l] = base[(long)z * SLICE + l];
    }
    __syncthreads();

    phaseP<N + 1>(&s0[l], &s1[l], g);  // z: column l

#pragma unroll
    for (int i = 0; i < 16; ++i) {
        int z = g * 16 + i;
        base[(long)z * SLICE + l] = s1[z * (N + 1) + l];
    }
}

// ---------------------------------------------------------------------------
// Kernel C: fused separable 3D x2 upsample.
// Coeff tile 8x8x16 (+2 halo each side) -> output tile 16x16x32.
// Even out 2m:  A*c[m-2] + C*c[m-1] + D*c[m] + B*c[m+1]
// Odd  out 2m+1:B*c[m-1] + D*c[m]   + C*c[m+1] + A*c[m+2]
// s_y aliases dead s_in; STG.128 streaming stores. 5 CTAs/SM (226KB smem).
// ---------------------------------------------------------------------------
#define CZ 8
#define CY 8
#define CX 16
#define IZ 12
#define IY 12
#define IX 20
#define SXW 36
#define UT 256

#define KA 0.00260416674427688122f
#define KB 0.0703125f
#define KC 0.31510416666666667f
#define KD 0.61197916666666663f

#define UP_EVEN(a, b_, c_, d_) fmaf(KA, (a), fmaf(KC, (b_), fmaf(KD, (c_), KB * (d_))))
#define UP_ODD(a, b_, c_, d_)  fmaf(KB, (a), fmaf(KD, (b_), fmaf(KC, (c_), KA * (d_))))

__device__ __forceinline__ float4 up_even4(float4 a, float4 b, float4 c, float4 d) {
    float4 r;
    r.x = UP_EVEN(a.x, b.x, c.x, d.x);
    r.y = UP_EVEN(a.y, b.y, c.y, d.y);
    r.z = UP_EVEN(a.z, b.z, c.z, d.z);
    r.w = UP_EVEN(a.w, b.w, c.w, d.w);
    return r;
}
__device__ __forceinline__ float4 up_odd4(float4 a, float4 b, float4 c, float4 d) {
    float4 r;
    r.x = UP_ODD(a.x, b.x, c.x, d.x);
    r.y = UP_ODD(a.y, b.y, c.y, d.y);
    r.z = UP_ODD(a.z, b.z, c.z, d.z);
    r.w = UP_ODD(a.w, b.w, c.w, d.w);
    return r;
}

// smem: s_x [IZ][IY][SXW] = 5184 floats, then region R = 6144 floats used as
// s_in [IZ][IY][IX] (2880, dead after stage X) then s_y [IZ][16][32].
__global__ void __launch_bounds__(UT, 5) upsample3d(float* __restrict__ out) {
    __shared__ float sm[5184 + 6144];  // 45.3 KB
    float* s_x = sm;
    float* s_in = sm + 5184;
    float* s_y = sm + 5184;

    const int txb = blockIdx.x;            // 0..5
    const int tyb = blockIdx.y;            // 0..11
    const int tzb = blockIdx.z % (N / CZ); // 0..11
    const int bc = blockIdx.z / (N / CZ);  // 0..5
    const int t = threadIdx.x;

    const float* src = g_coef + (long)bc * VOL;
    const int gz0 = tzb * CZ - 2, gy0 = tyb * CY - 2, gx0 = txb * CX - 2;

    // Halo load with edge clamp: 2880 elems
#pragma unroll
    for (int e = t; e < IZ * IY * IX; e += UT) {
        int lx = e % IX;
        int r = e / IX;
        int ly = r % IY;
        int lz = r / IY;
        int gz = min(max(gz0 + lz, 0), N - 1);
        int gy = min(max(gy0 + ly, 0), N - 1);
        int gx = min(max(gx0 + lx, 0), N - 1);
        s_in[(lz * IY + ly) * IX + lx] = src[((long)gz * N + gy) * N + gx];
    }
    __syncthreads();

    // Stage X: 144 lines x 4 quads = 576 tasks; 8 in -> 8 out each (float4 IO)
#pragma unroll
    for (int e = t; e < IZ * IY * 4; e += UT) {
        int q = e & 3;
        int line = e >> 2;  // lz*IY + ly
        const float* row = &s_in[line * IX + 4 * q];
        const float4 p0 = *(const float4*)row;
        const float4 p1 = *(const float4*)(row + 4);
        const float v0 = p0.x, v1 = p0.y, v2 = p0.z, v3 = p0.w;
        const float v4 = p1.x, v5 = p1.y, v6 = p1.z, v7 = p1.w;
        float4 r0, r1;
        r0.x = UP_EVEN(v0, v1, v2, v3);
        r0.y = UP_ODD(v1, v2, v3, v4);
        r0.z = UP_EVEN(v1, v2, v3, v4);
        r0.w = UP_ODD(v2, v3, v4, v5);
        r1.x = UP_EVEN(v2, v3, v4, v5);
        r1.y = UP_ODD(v3, v4, v5, v6);
        r1.z = UP_EVEN(v3, v4, v5, v6);
        r1.w = UP_ODD(v4, v5, v6, v7);
        *(float4*)&s_x[line * SXW + 8 * q] = r0;
        *(float4*)&s_x[line * SXW + 8 * q + 4] = r1;
    }
    __syncthreads();  // also: s_in reads complete before s_y overwrites region

    // Stage Y: (lz 0..11, xo 0..31) = 384 tasks; window 12 -> 16 y-outputs
#pragma unroll
    for (int e = t; e < IZ * 32; e += UT) {
        const int xo = e & 31, lz = e >> 5;
        float u[IY];
#pragma unroll
        for (int h = 0; h < IY; ++h) u[h] = s_x[(lz * IY + h) * SXW + xo];
#pragma unroll
        for (int h = 0; h < CY; ++h) {
            s_y[(lz * 16 + 2 * h) * 32 + xo] = UP_EVEN(u[h], u[h + 1], u[h + 2], u[h + 3]);
            s_y[(lz * 16 + 2 * h + 1) * 32 + xo] = UP_ODD(u[h + 1], u[h + 2], u[h + 3], u[h + 4]);
        }
    }
    __syncthreads();

    // Stage Z: thread (zq, yo, xq) -> 8 z-outputs x float4; STG.128 streaming
    {
        const int xq = t & 7, yo = (t >> 3) & 15, zq = t >> 7;  // zq 0..1
        float4 u[8];
#pragma unroll
        for (int i = 0; i < 8; ++i)
            u[i] = *(const float4*)&s_y[((4 * zq + i) * 16 + yo) * 32 + 4 * xq];
        const long base_out = (((long)bc * NO + (long)tzb * (2 * CZ)) * NO +
                               (long)tyb * (2 * CY) + yo) * NO + (long)txb * (2 * CX) + 4 * xq;
#pragma unroll
        for (int hh = 0; hh < 4; ++hh) {
            float4 o0 = up_even4(u[hh], u[hh + 1], u[hh + 2], u[hh + 3]);
            float4 o1 = up_odd4(u[hh + 1], u[hh + 2], u[hh + 3], u[hh + 4]);
            const long zo = 2 * (4 * zq + hh);
            __stcs((float4*)&out[base_out + zo * NO * NO], o0);
            __stcs((float4*)&out[base_out + (zo + 1) * NO * NO], o1);
        }
    }
}

// ---------------------------------------------------------------------------
extern "C" void kernel_launch(void* const* d_in, const int* in_sizes, int n_in,
                              void* d_out, int out_size) {
    const float* in = (const float*)d_in[0];
    float* out = (float*)d_out;

    cudaFuncSetAttribute(prefilter_xy, cudaFuncAttributeMaxDynamicSharedMemorySize, PF_SMEM);
    cudaFuncSetAttribute(prefilter_z, cudaFuncAttributeMaxDynamicSharedMemorySize, PF_SMEM);

    prefilter_xy<<<NB * N, PF_THREADS, PF_SMEM>>>(in);
    prefilter_z<<<NB * N, PF_THREADS, PF_SMEM>>>();
    upsample3d<<<dim3(N / CX, N / CY, NB * (N / CZ)), UT>>>(out);
}

// round 8
// speedup vs baseline: 1.4045x; 1.0614x over previous
#include <cuda_runtime.h>

// Problem constants: volume (2,3,96,96,96) fp32 -> (2,3,192,192,192) fp32
#define NB 6
#define N 96
#define NO 192
#define SLICE (N * N)
#define VOL (N * N * N)

// Scratch for prefiltered spline coefficients (21.2 MB)
__device__ float g_coef[NB * VOL];

// ---------------------------------------------------------------------------
// Composite cubic B-spline prefilter: causal o anticausal == symmetric FIR
//   h[k] = sqrt(3) * p^|k|,  p = sqrt(3)-2, truncated at |k|<=8
//   (tail ~3.4e-5 per axis, ~1e-4 over 3 axes; tolerance is 1e-3).
// Left mirror boundary exact via mirrored reads; right boundary via
// two-stage 9-tap causal -> clamp -> 9-tap anticausal. Taps are immediates.
// ---------------------------------------------------------------------------

// 17-tap symmetric composite, center at w[8]
__device__ __forceinline__ float dotH(const float* w) {
    float a =                4.6027405e-5f * w[0];
    a = fmaf(-1.7177666e-4f, w[1],  a);
    a = fmaf( 6.4104185e-4f, w[2],  a);
    a = fmaf(-2.3923958e-3f, w[3],  a);
    a = fmaf( 8.9283344e-3f, w[4],  a);
    a = fmaf(-3.3320996e-2f, w[5],  a);
    a = fmaf( 1.2435565e-1f, w[6],  a);
    a = fmaf(-4.6410162e-1f, w[7],  a);
    a = fmaf( 1.7320508e0f,  w[8],  a);
    a = fmaf(-4.6410162e-1f, w[9],  a);
    a = fmaf( 1.2435565e-1f, w[10], a);
    a = fmaf(-3.3320996e-2f, w[11], a);
    a = fmaf( 8.9283344e-3f, w[12], a);
    a = fmaf(-2.3923958e-3f, w[13], a);
    a = fmaf( 6.4104185e-4f, w[14], a);
    a = fmaf(-1.7177666e-4f, w[15], a);
    a = fmaf( 4.6027405e-5f, w[16], a);
    return a;
}

// 9-tap causal: c[i] = 6*sum_{k=0..8} p^k x[i-k]; w[k] = x[i-8+k]
__device__ __forceinline__ float dotA(const float* w) {
    float acc =              1.5943030e-4f * w[0];
    acc = fmaf(-5.9500220e-4f, w[1], acc);
    acc = fmaf( 2.2205777e-3f, w[2], acc);
    acc = fmaf(-8.2873086e-3f, w[3], acc);
    acc = fmaf( 3.0928657e-2f, w[4], acc);
    acc = fmaf(-1.1542732e-1f, w[5], acc);
    acc = fmaf( 4.3078062e-1f, w[6], acc);
    acc = fmaf(-1.6076952e0f,  w[7], acc);
    acc = fmaf( 6.0f,          w[8], acc);
    return acc;
}

// 9-tap anticausal: y[i] = sum_{j=0..8} (-p^{j+1}) c[i+j]; w[j] = c[i+j]
__device__ __forceinline__ float dotB(const float* w) {
    float acc =              7.1198750e-6f * w[8];
    acc = fmaf(-2.6571710e-5f, w[7], acc);
    acc = fmaf( 9.9170000e-5f, w[6], acc);
    acc = fmaf(-3.7009628e-4f, w[5], acc);
    acc = fmaf( 1.3812181e-3f, w[4], acc);
    acc = fmaf(-5.1547761e-3f, w[3], acc);
    acc = fmaf( 1.9237886e-2f, w[2], acc);
    acc = fmaf(-7.1796770e-2f, w[1], acc);
    acc = fmaf( 2.6794919e-1f, w[0], acc);
    return acc;
}

// One prefilter phase for group g (16 outputs) of a 96-line, stride S.
// Reads bsrc, writes bdst (ping-pong -> no internal barrier needed).
template <int S>
__device__ __forceinline__ void phaseP(const float* bsrc, float* bdst, int g) {
    float yv[16];
    if (g == 0) {  // left edge: composite on mirror-extended reads (exact)
        float w[32];
#pragma unroll
        for (int k = 0; k < 32; ++k) {
            int j = k - 8;
            int idx = j ^ (j >> 31);  // mirror x[-m] = x[m-1]
            w[k] = bsrc[idx * S];
        }
#pragma unroll
        for (int m = 0; m < 16; ++m) yv[m] = dotH(w + m);
    } else if (g < 5) {  // interior: window x[i0-8 .. i0+23]
        float w[32];
#pragma unroll
        for (int k = 0; k < 32; ++k) w[k] = bsrc[(g * 16 - 8 + k) * S];
#pragma unroll
        for (int m = 0; m < 16; ++m) yv[m] = dotH(w + m);
    } else {  // right edge: 80..83 composite; 84..95 exact two-stage
        float xw[24];  // x[72..95]
#pragma unroll
        for (int k = 0; k < 24; ++k) xw[k] = bsrc[(72 + k) * S];
#pragma unroll
        for (int m = 0; m < 4; ++m) yv[m] = dotH(xw + m);  // outputs 80..83
        float ce[20];  // c[84..95] then clamp-extension c[95] x8
#pragma unroll
        for (int j = 0; j < 12; ++j) ce[j] = dotA(xw + 4 + j);
#pragma unroll
        for (int j = 12; j < 20; ++j) ce[j] = ce[11];
#pragma unroll
        for (int m = 0; m < 12; ++m) yv[4 + m] = dotB(ce + m);
    }
#pragma unroll
    for (int m = 0; m < 16; ++m) bdst[(g * 16 + m) * S] = yv[m];
}

#define PF_THREADS 576  // 96 lines x 6 groups
#define PF_SMEM (2 * N * (N + 1) * 4)  // ping-pong pair, bytes

// ---------------------------------------------------------------------------
// Kernel A: prefilter x then y, one CTA per (b,c,z) slice. (576,2): proven.
// ---------------------------------------------------------------------------
__global__ void __launch_bounds__(PF_THREADS, 2) prefilter_xy(const float* __restrict__ in) {
    extern __shared__ float sm[];
    float* s0 = sm;
    float* s1 = sm + N * (N + 1);
    const int slice = blockIdx.x;
    const float* src = in + (long)slice * SLICE;
    float* dst = g_coef + (long)slice * SLICE;
    const int t = threadIdx.x;
    const int g = t / N, l = t % N;

#pragma unroll
    for (int i = 0; i < 16; ++i) {
        int r = g * 16 + i;
        s0[r * (N + 1) + l] = src[r * N + l];
    }
    __syncthreads();

    phaseP<1>(&s0[l * (N + 1)], &s1[l * (N + 1)], g);  // x: row l
    __syncthreads();
    phaseP<N + 1>(&s1[l], &s0[l], g);                  // y: column l

    // store reads only elements this thread just wrote -> no barrier
#pragma unroll
    for (int i = 0; i < 16; ++i) {
        int r = g * 16 + i;
        dst[r * N + l] = s0[r * (N + 1) + l];
    }
}

// ---------------------------------------------------------------------------
// Kernel B: prefilter along z, one CTA per (b,c,y) slice. 1 barrier.
// ---------------------------------------------------------------------------
__global__ void __launch_bounds__(PF_THREADS, 2) prefilter_z() {
    extern __shared__ float sm[];
    float* s0 = sm;
    float* s1 = sm + N * (N + 1);
    const int bc = blockIdx.x / N;
    const int y = blockIdx.x % N;
    float* base = g_coef + (long)bc * VOL + (long)y * N;
    const int t = threadIdx.x;
    const int g = t / N, l = t % N;  // l = x index

#pragma unroll
    for (int i = 0; i < 16; ++i) {
        int z = g * 16 + i;
        s0[z * (N + 1) + l] = base[(long)z * SLICE + l];
    }
    __syncthreads();

    phaseP<N + 1>(&s0[l], &s1[l], g);  // z: column l

#pragma unroll
    for (int i = 0; i < 16; ++i) {
        int z = g * 16 + i;
        base[(long)z * SLICE + l] = s1[z * (N + 1) + l];
    }
}

// ---------------------------------------------------------------------------
// Kernel C: fused separable 3D x2 upsample. (unchanged, near DRAM floor)
// Coeff tile 8x8x16 (+2 halo each side) -> output tile 16x16x32.
// Even out 2m:  A*c[m-2] + C*c[m-1] + D*c[m] + B*c[m+1]
// Odd  out 2m+1:B*c[m-1] + D*c[m]   + C*c[m+1] + A*c[m+2]
// s_y aliases dead s_in; STG.128 streaming stores. 5 CTAs/SM.
// ---------------------------------------------------------------------------
#define CZ 8
#define CY 8
#define CX 16
#define IZ 12
#define IY 12
#define IX 20
#define SXW 36
#define UT 256

#define KA 0.00260416674427688122f
#define KB 0.0703125f
#define KC 0.31510416666666667f
#define KD 0.61197916666666663f

#define UP_EVEN(a, b_, c_, d_) fmaf(KA, (a), fmaf(KC, (b_), fmaf(KD, (c_), KB * (d_))))
#define UP_ODD(a, b_, c_, d_)  fmaf(KB, (a), fmaf(KD, (b_), fmaf(KC, (c_), KA * (d_))))

__device__ __forceinline__ float4 up_even4(float4 a, float4 b, float4 c, float4 d) {
    float4 r;
    r.x = UP_EVEN(a.x, b.x, c.x, d.x);
    r.y = UP_EVEN(a.y, b.y, c.y, d.y);
    r.z = UP_EVEN(a.z, b.z, c.z, d.z);
    r.w = UP_EVEN(a.w, b.w, c.w, d.w);
    return r;
}
__device__ __forceinline__ float4 up_odd4(float4 a, float4 b, float4 c, float4 d) {
    float4 r;
    r.x = UP_ODD(a.x, b.x, c.x, d.x);
    r.y = UP_ODD(a.y, b.y, c.y, d.y);
    r.z = UP_ODD(a.z, b.z, c.z, d.z);
    r.w = UP_ODD(a.w, b.w, c.w, d.w);
    return r;
}

__global__ void __launch_bounds__(UT, 5) upsample3d(float* __restrict__ out) {
    __shared__ float sm[5184 + 6144];  // 45.3 KB
    float* s_x = sm;
    float* s_in = sm + 5184;
    float* s_y = sm + 5184;

    const int txb = blockIdx.x;            // 0..5
    const int tyb = blockIdx.y;            // 0..11
    const int tzb = blockIdx.z % (N / CZ); // 0..11
    const int bc = blockIdx.z / (N / CZ);  // 0..5
    const int t = threadIdx.x;

    const float* src = g_coef + (long)bc * VOL;
    const int gz0 = tzb * CZ - 2, gy0 = tyb * CY - 2, gx0 = txb * CX - 2;

#pragma unroll
    for (int e = t; e < IZ * IY * IX; e += UT) {
        int lx = e % IX;
        int r = e / IX;
        int ly = r % IY;
        int lz = r / IY;
        int gz = min(max(gz0 + lz, 0), N - 1);
        int gy = min(max(gy0 + ly, 0), N - 1);
        int gx = min(max(gx0 + lx, 0), N - 1);
        s_in[(lz * IY + ly) * IX + lx] = src[((long)gz * N + gy) * N + gx];
    }
    __syncthreads();

    // Stage X: 144 lines x 4 quads = 576 tasks; 8 in -> 8 out each
#pragma unroll
    for (int e = t; e < IZ * IY * 4; e += UT) {
        int q = e & 3;
        int line = e >> 2;
        const float* row = &s_in[line * IX + 4 * q];
        const float4 p0 = *(const float4*)row;
        const float4 p1 = *(const float4*)(row + 4);
        const float v0 = p0.x, v1 = p0.y, v2 = p0.z, v3 = p0.w;
        const float v4 = p1.x, v5 = p1.y, v6 = p1.z, v7 = p1.w;
        float4 r0, r1;
        r0.x = UP_EVEN(v0, v1, v2, v3);
        r0.y = UP_ODD(v1, v2, v3, v4);
        r0.z = UP_EVEN(v1, v2, v3, v4);
        r0.w = UP_ODD(v2, v3, v4, v5);
        r1.x = UP_EVEN(v2, v3, v4, v5);
        r1.y = UP_ODD(v3, v4, v5, v6);
        r1.z = UP_EVEN(v3, v4, v5, v6);
        r1.w = UP_ODD(v4, v5, v6, v7);
        *(float4*)&s_x[line * SXW + 8 * q] = r0;
        *(float4*)&s_x[line * SXW + 8 * q + 4] = r1;
    }
    __syncthreads();

    // Stage Y: 384 tasks; window 12 -> 16 y-outputs
#pragma unroll
    for (int e = t; e < IZ * 32; e += UT) {
        const int xo = e & 31, lz = e >> 5;
        float u[IY];
#pragma unroll
        for (int h = 0; h < IY; ++h) u[h] = s_x[(lz * IY + h) * SXW + xo];
#pragma unroll
        for (int h = 0; h < CY; ++h) {
            s_y[(lz * 16 + 2 * h) * 32 + xo] = UP_EVEN(u[h], u[h + 1], u[h + 2], u[h + 3]);
            s_y[(lz * 16 + 2 * h + 1) * 32 + xo] = UP_ODD(u[h + 1], u[h + 2], u[h + 3], u[h + 4]);
        }
    }
    __syncthreads();

    // Stage Z: STG.128 streaming stores
    {
        const int xq = t & 7, yo = (t >> 3) & 15, zq = t >> 7;
        float4 u[8];
#pragma unroll
        for (int i = 0; i < 8; ++i)
            u[i] = *(const float4*)&s_y[((4 * zq + i) * 16 + yo) * 32 + 4 * xq];
        const long base_out = (((long)bc * NO + (long)tzb * (2 * CZ)) * NO +
                               (long)tyb * (2 * CY) + yo) * NO + (long)txb * (2 * CX) + 4 * xq;
#pragma unroll
        for (int hh = 0; hh < 4; ++hh) {
            float4 o0 = up_even4(u[hh], u[hh + 1], u[hh + 2], u[hh + 3]);
            float4 o1 = up_odd4(u[hh + 1], u[hh + 2], u[hh + 3], u[hh + 4]);
            const long zo = 2 * (4 * zq + hh);
            __stcs((float4*)&out[base_out + zo * NO * NO], o0);
            __stcs((float4*)&out[base_out + (zo + 1) * NO * NO], o1);
        }
    }
}

// ---------------------------------------------------------------------------
extern "C" void kernel_launch(void* const* d_in, const int* in_sizes, int n_in,
                              void* d_out, int out_size) {
    const float* in = (const float*)d_in[0];
    float* out = (float*)d_out;

    cudaFuncSetAttribute(prefilter_xy, cudaFuncAttributeMaxDynamicSharedMemorySize, PF_SMEM);
    cudaFuncSetAttribute(prefilter_z, cudaFuncAttributeMaxDynamicSharedMemorySize, PF_SMEM);

    prefilter_xy<<<NB * N, PF_THREADS, PF_SMEM>>>(in);
    prefilter_z<<<NB * N, PF_THREADS, PF_SMEM>>>();
    upsample3d<<<dim3(N / CX, N / CY, NB * (N / CZ)), UT>>>(out);
}